// round 2
// baseline (speedup 1.0000x reference)
#include <cuda_runtime.h>
#include <cuda_bf16.h>

// 3D ROI pooling, corner-split version.
//   img:  (1, 256, 256, 256, 8) fp32, layout ((ix*256+iy)*256+iz)*8 + c
//   rois: (1, 64, 6) int32  [x, y, z, w, h, d]
//   out:  (1, 64, 7, 7, 7, 8) fp32
//
// One thread per (cell, channel-half, xy_corner): 64*343*2*4 = 175,616 threads
// (5488 full warps). Each thread loads its corner's z0/z1 float4, z-blends,
// scales by its own wx*wy, then a 4-lane shfl_xor butterfly sums the four
// (x,y) corner partials. Lane groups of 4 are warp-aligned.

#define NUM_ROIS 64
#define PS 7
#define CELLS (PS * PS * PS)            // 343
#define DIM 256

__global__ void roi_pool3d_kernel(const float* __restrict__ img,
                                  const int* __restrict__ rois,
                                  float* __restrict__ out)
{
    int tid = blockIdx.x * blockDim.x + threadIdx.x;
    const int total = NUM_ROIS * CELLS * 2 * 4;   // 175616
    if (tid >= total) return;

    int xy   = tid & 3;           // 0..3 : (bx, by) corner
    int vec  = tid >> 2;          // output float4 index = cell*2 + half
    int half = vec & 1;
    int cell = vec >> 1;
    int roi  = cell / CELLS;
    int rem  = cell - roi * CELLS;
    int px   = rem / (PS * PS);
    int r2   = rem - px * (PS * PS);
    int py   = r2 / PS;
    int pz   = r2 - py * PS;

    int bx = xy & 1;
    int by = xy >> 1;

    const int* r = rois + roi * 6;
    int x = r[0], y = r[1], z = r[2];
    int w = r[3], h = r[4], d = r[5];

    // --- axis coords (match reference fp32 arithmetic) ---
    float sx = (float)px * ((float)w / (float)PS);
    int ix0 = (int)floorf(sx);
    float fx = sx - (float)ix0;
    int ix1 = min(ix0 + 1, w - 1);
    ix0 = min(ix0, w - 1);

    float sy = (float)py * ((float)h / (float)PS);
    int iy0 = (int)floorf(sy);
    float fy = sy - (float)iy0;
    int iy1 = min(iy0 + 1, h - 1);
    iy0 = min(iy0, h - 1);

    float sz = (float)pz * ((float)d / (float)PS);
    int iz0 = (int)floorf(sz);
    float fz = sz - (float)iz0;
    int iz1 = min(iz0 + 1, d - 1);
    iz0 = min(iz0, d - 1);

    int ix = x + (bx ? ix1 : ix0);
    int iy = y + (by ? iy1 : iy0);
    int jz0 = z + iz0;
    int jz1 = z + iz1;

    float wx = bx ? fx : (1.0f - fx);
    float wy = by ? fy : (1.0f - fy);
    float wxy = wx * wy;
    float gz = 1.0f - fz;

    // float4 index: ((ix*256+iy)*256+iz)*2 + half
    const float4* __restrict__ base = (const float4*)img;
    size_t rowb = (size_t)(ix * DIM + iy) * DIM;
    float4 v0 = base[(rowb + jz0) * 2 + half];
    float4 v1 = base[(rowb + jz1) * 2 + half];

    // z-blend, then apply this corner's (x,y) weight
    float4 p;
    p.x = (v0.x * gz + v1.x * fz) * wxy;
    p.y = (v0.y * gz + v1.y * fz) * wxy;
    p.z = (v0.z * gz + v1.z * fz) * wxy;
    p.w = (v0.w * gz + v1.w * fz) * wxy;

    // sum the 4 corner partials across lanes (groups of 4, warp-aligned)
    const unsigned m = 0xFFFFFFFFu;
    p.x += __shfl_xor_sync(m, p.x, 1);
    p.y += __shfl_xor_sync(m, p.y, 1);
    p.z += __shfl_xor_sync(m, p.z, 1);
    p.w += __shfl_xor_sync(m, p.w, 1);
    p.x += __shfl_xor_sync(m, p.x, 2);
    p.y += __shfl_xor_sync(m, p.y, 2);
    p.z += __shfl_xor_sync(m, p.z, 2);
    p.w += __shfl_xor_sync(m, p.w, 2);

    if (xy == 0) {
        ((float4*)out)[vec] = p;
    }
}

extern "C" void kernel_launch(void* const* d_in, const int* in_sizes, int n_in,
                              void* d_out, int out_size)
{
    const float* img  = (const float*)d_in[0];
    const int*   rois = (const int*)d_in[1];
    float*       out  = (float*)d_out;

    const int total = NUM_ROIS * CELLS * 2 * 4;   // 175616 threads
    const int threads = 256;
    const int blocks = (total + threads - 1) / threads;   // 686
    roi_pool3d_kernel<<<blocks, threads>>>(img, rois, out);
}